// round 1
// baseline (speedup 1.0000x reference)
#include <cuda_runtime.h>
#include <cstdint>

#define BATCH 16
#define NA    8400
#define NC    80
#define NM    24
#define KTOP  13
#define REG   16
#define CHUNKS 33   // ceil(8400/256)

// ---------------- device scratch (no allocs allowed) ----------------
__device__ float g_cmask[BATCH * NC];
__device__ int   g_labels[BATCH * NM];
__device__ int   g_modes[2];
__device__ float g_cand_val[BATCH * NM * KTOP];
__device__ int   g_cand_idx[BATCH * NM * KTOP];
__device__ unsigned long long g_best[BATCH * NA];
__device__ float g_partial[BATCH][CHUNKS][8];

// ---------------- dtype auto-detection for class_mask / gt_labels ----------------
// class_mask[:,0] is guaranteed True by setup_inputs.
__global__ void k_mode(const void* cm, const void* lab) {
    const unsigned* cw = (const unsigned*)cm;
    int mode;
    if (cw[0] == 0x3F800000u) {
        mode = 0;                      // float32 (True == 1.0f)
    } else {
        mode = 1;                      // assume int32 (words all 0/1)
        for (int i = 0; i < 80; i++) { // 320 bytes: safe for both int32 and uint8 layouts
            if (cw[i] > 1u) { mode = 2; break; }   // uint8-packed
        }
    }
    g_modes[0] = mode;
    const unsigned* lw = (const unsigned*)lab;
    int lm = 0;                        // 0 = int32, 1 = float32
    for (int i = 0; i < BATCH * NM; i++) {
        if (lw[i] > 1000u) { lm = 1; break; }      // labels < 80 as ints; as floats >= 0x3F800000
    }
    g_modes[1] = lm;
}

__global__ void k_norm(const void* cm, const void* lab) {
    int t = threadIdx.x;
    int mode = g_modes[0];
    for (int i = t; i < BATCH * NC; i += blockDim.x) {
        float v;
        if (mode == 0)       v = ((const float*)cm)[i];
        else if (mode == 1)  v = (float)(((const int*)cm)[i] != 0);
        else                 v = (float)(((const unsigned char*)cm)[i] != 0);
        g_cmask[i] = (v != 0.0f) ? 1.0f : 0.0f;
    }
    int lm = g_modes[1];
    for (int i = t; i < BATCH * NM; i += blockDim.x) {
        g_labels[i] = lm ? (int)(((const float*)lab)[i]) : ((const int*)lab)[i];
    }
}

// ---------------- helpers ----------------
__device__ __forceinline__ float sigmoidf(float x) { return 1.0f / (1.0f + expf(-x)); }

__device__ __forceinline__ float iou_box(float a0, float a1, float a2, float a3,
                                         float b0, float b1, float b2, float b3) {
    float lt0 = fmaxf(a0, b0), lt1 = fmaxf(a1, b1);
    float rb0 = fminf(a2, b2), rb1 = fminf(a3, b3);
    float w = fmaxf(rb0 - lt0, 0.0f), h = fmaxf(rb1 - lt1, 0.0f);
    float inter = w * h;
    float aa = fmaxf(a2 - a0, 0.0f) * fmaxf(a3 - a1, 0.0f);
    float ab = fmaxf(b2 - b0, 0.0f) * fmaxf(b3 - b1, 0.0f);
    return inter / (aa + ab - inter + 1e-7f);
}

// ---------------- per-(image,GT) align + top-13 ----------------
__global__ __launch_bounds__(256) void k_align(const float* __restrict__ pb,
                                               const float* __restrict__ ps,
                                               const float* __restrict__ ap,
                                               const float* __restrict__ gtb) {
    __shared__ float s_align[NA];
    __shared__ float sv[256];
    __shared__ int   si[256];

    int blk = blockIdx.x;
    int b = blk / NM, g = blk % NM;
    int t = threadIdx.x;

    int lab = g_labels[b * NM + g];
    int labc = min(max(lab, 0), NC - 1);
    bool valid = (lab >= 0) && (lab < NC) && (g_cmask[b * NC + labc] != 0.0f);

    const float* gbp = gtb + (size_t)(b * NM + g) * 4;
    float gb0 = gbp[0], gb1 = gbp[1], gb2 = gbp[2], gb3 = gbp[3];
    const float* pbb = pb + (size_t)b * NA * 4;
    const float* psb = ps + (size_t)b * NA * NC + labc;

    for (int i = t; i < NA; i += 256) {
        float axp = ap[2 * i], ayp = ap[2 * i + 1];
        float al = -1.0f;
        bool inside = (axp >= gb0) && (axp <= gb2) && (ayp >= gb1) && (ayp <= gb3);
        if (inside && valid) {
            const float* bx = pbb + (size_t)i * 4;
            float iou = iou_box(bx[0], bx[1], bx[2], bx[3], gb0, gb1, gb2, gb3);
            float cls = sigmoidf(psb[(size_t)i * NC]);
            al = cls * powf(iou, 6.0f);
        }
        s_align[i] = al;
    }
    __syncthreads();

    for (int k = 0; k < KTOP; k++) {
        float bv = -3.0f; int bi = NA;
        for (int i = t; i < NA; i += 256) {
            float v = s_align[i];
            if (v > bv || (v == bv && i < bi)) { bv = v; bi = i; }
        }
        sv[t] = bv; si[t] = bi;
        __syncthreads();
        for (int s = 128; s > 0; s >>= 1) {
            if (t < s) {
                float v2 = sv[t + s]; int i2 = si[t + s];
                if (v2 > sv[t] || (v2 == sv[t] && i2 < si[t])) { sv[t] = v2; si[t] = i2; }
            }
            __syncthreads();
        }
        if (t == 0) {
            g_cand_val[blk * KTOP + k] = sv[0];
            g_cand_idx[blk * KTOP + k] = si[0];
            s_align[si[0]] = -2.0f;   // remove from further consideration
        }
        __syncthreads();
    }
}

// ---------------- combine candidates: per-anchor best (deterministic atomicMax) ----------------
__global__ __launch_bounds__(256) void k_scatter() {
    int b = blockIdx.x, t = threadIdx.x;
    for (int i = t; i < NA; i += 256) g_best[b * NA + i] = 0ull;
    __syncthreads();
    for (int e = t; e < NM * KTOP; e += 256) {
        int g = e / KTOP;
        int off = (b * NM + g) * KTOP + (e % KTOP);
        float v = g_cand_val[off];
        if (v >= 0.0f) {   // real candidates have align >= 0; excluded anchors got -1
            int idx = g_cand_idx[off];
            unsigned long long key =
                ((unsigned long long)__float_as_uint(v) << 32) | (unsigned)(NM - g);
            atomicMax(&g_best[b * NA + idx], key);
        }
    }
}

// ---------------- per-anchor loss terms, block-reduced per image chunk ----------------
__global__ __launch_bounds__(256) void k_loss(const float* __restrict__ pb,
                                              const float* __restrict__ ps,
                                              const float* __restrict__ pobj,
                                              const float* __restrict__ ap,
                                              const float* __restrict__ st,
                                              const float* __restrict__ bd,
                                              const float* __restrict__ gtb) {
    int b = blockIdx.y;
    int n = blockIdx.x * 256 + threadIdx.x;

    // acc: 0 focal, 1 cnt, 2 (1-ciou), 3 matched iou, 4 ce, 5 dfl, 6 pos, 7 neg
    float acc[8];
#pragma unroll
    for (int q = 0; q < 8; q++) acc[q] = 0.0f;

    if (n < NA) {
        unsigned long long key = g_best[b * NA + n];
        bool fg = (key != 0ull);

        // objectness focal
        float x = pobj[(size_t)b * NA + n];
        float tt = fg ? 1.0f : 0.0f;
        float ce_o = fmaxf(x, 0.0f) - x * tt + log1pf(expf(-fabsf(x)));
        float prob_o = sigmoidf(x);
        float p_t = fg ? prob_o : (1.0f - prob_o);
        float af  = fg ? 0.25f  : 0.75f;
        float om  = 1.0f - p_t;
        acc[0] = ce_o * af * om * om;

        // class scores: masked max (+ logsumexp for fg)
        const float* srow = ps + ((size_t)b * NA + n) * NC;
        const float* cmrow = g_cmask + b * NC;
        float mx = -1e30f;
#pragma unroll 4
        for (int c = 0; c < NC; c++) {
            if (cmrow[c] != 0.0f) mx = fmaxf(mx, srow[c]);
        }

        if (!fg) {
            acc[7] = prob_o * sigmoidf(mx);          // obj * neg_best
        } else {
            int g = NM - (int)(key & 0xFFull);
            int lab = g_labels[b * NM + g];
            lab = min(max(lab, 0), NC - 1);
            float slab = srow[lab];
            float sum = 0.0f;
            for (int c = 0; c < NC; c++) {
                if (cmrow[c] != 0.0f) sum += expf(srow[c] - mx);
            }
            float lse = mx + logf(sum);
            acc[4] = lse - slab;                     // CE
            acc[6] = prob_o * sigmoidf(slab);        // pos_joint
            acc[1] = 1.0f;                           // cnt

            const float* a = pb + ((size_t)b * NA + n) * 4;
            const float* tb = gtb + (size_t)(b * NM + g) * 4;
            float a0 = a[0], a1 = a[1], a2 = a[2], a3 = a[3];
            float b0 = tb[0], b1 = tb[1], b2 = tb[2], b3 = tb[3];

            float iou = iou_box(a0, a1, a2, a3, b0, b1, b2, b3);
            acc[3] = iou;                            // matched iou

            // CIoU
            float cw = fmaxf(a2, b2) - fminf(a0, b0);
            float ch = fmaxf(a3, b3) - fminf(a1, b1);
            float c2 = cw * cw + ch * ch + 1e-7f;
            float dx = a0 + a2 - b0 - b2;
            float dy = a1 + a3 - b1 - b3;
            float rho2 = (dx * dx + dy * dy) * 0.25f;
            float w1 = a2 - a0, h1 = a3 - a1;
            float w2 = b2 - b0, h2 = b3 - b1;
            float dat = atanf(w2 / (h2 + 1e-7f)) - atanf(w1 / (h1 + 1e-7f));
            float v = (4.0f / (3.14159265358979323846f * 3.14159265358979323846f)) * dat * dat;
            float alpha = v / (v - iou + 1.0f + 1e-7f);
            float ciou = iou - rho2 / c2 - v * alpha;
            acc[2] = 1.0f - ciou;

            // DFL
            float axp = ap[2 * n], ayp = ap[2 * n + 1];
            float s = st[n];
            float tgt[4];
            tgt[0] = (axp - b0) / s;
            tgt[1] = (ayp - b1) / s;
            tgt[2] = (b2 - axp) / s;
            tgt[3] = (b3 - ayp) / s;
            const float* lrow = bd + ((size_t)b * NA + n) * (4 * REG);
            float dfl = 0.0f;
#pragma unroll
            for (int j = 0; j < 4; j++) {
                float tv = fminf(fmaxf(tgt[j], 0.0f), (float)(REG - 1) - 0.01f);
                int tl = (int)tv;
                int tr = min(tl + 1, REG - 1);
                float wl = (float)tr - tv;
                float wr = 1.0f - wl;
                const float* lg = lrow + j * REG;
                float m2 = -1e30f;
#pragma unroll
                for (int i = 0; i < REG; i++) m2 = fmaxf(m2, lg[i]);
                float s2 = 0.0f;
#pragma unroll
                for (int i = 0; i < REG; i++) s2 += expf(lg[i] - m2);
                float lse2 = m2 + logf(s2);
                dfl += (lse2 - lg[tl]) * wl + (lse2 - lg[tr]) * wr;
            }
            acc[5] = dfl;
        }
    }

    // deterministic block tree reduction
    __shared__ float red[256];
    for (int q = 0; q < 8; q++) {
        red[threadIdx.x] = acc[q];
        __syncthreads();
        for (int s = 128; s > 0; s >>= 1) {
            if (threadIdx.x < s) red[threadIdx.x] += red[threadIdx.x + s];
            __syncthreads();
        }
        if (threadIdx.x == 0) g_partial[b][blockIdx.x][q] = red[0];
        __syncthreads();
    }
}

// ---------------- final deterministic combine ----------------
__global__ void k_final(float* __restrict__ out) {
    __shared__ float img[BATCH][8];
    int t = threadIdx.x;
    if (t < BATCH) {
        float s[8];
#pragma unroll
        for (int q = 0; q < 8; q++) s[q] = 0.0f;
        for (int c = 0; c < CHUNKS; c++)
#pragma unroll
            for (int q = 0; q < 8; q++) s[q] += g_partial[t][c][q];
#pragma unroll
        for (int q = 0; q < 8; q++) img[t][q] = s[q];
    }
    __syncthreads();
    if (t == 0) {
        float tot_obj = 0, tot_iou = 0, tot_match = 0, tot_dfl = 0;
        float tot_pos = 0, miou = 0, pos = 0, neg = 0;
        for (int b = 0; b < BATCH; b++) {
            float cnt = img[b][1];
            float cs = fmaxf(cnt, 1.0f);
            tot_obj   += img[b][0] / (float)NA;
            tot_iou   += img[b][2] / cs;
            tot_match += img[b][4] / cs;
            tot_dfl   += img[b][5] / (4.0f * cs);
            tot_pos   += cnt;
            miou += img[b][3];
            pos  += img[b][6];
            neg  += img[b][7];
        }
        float tot_neg = (float)(BATCH * NA) - tot_pos;
        float nb = (float)BATCH;
        float loss = (1.0f * tot_obj + 1.0f * tot_match + 7.5f * tot_iou + 1.5f * tot_dfl) / nb;
        out[0] = loss;
        out[1] = tot_obj / nb;
        out[2] = tot_match / nb;
        out[3] = tot_iou / nb;
        out[4] = tot_dfl / nb;
        out[5] = tot_pos;
        out[6] = tot_neg;
        out[7] = pos / fmaxf(tot_pos, 1.0f);
        out[8] = neg / fmaxf(tot_neg, 1.0f);
        out[9] = miou / fmaxf(tot_pos, 1.0f);
    }
}

// ---------------- launch ----------------
extern "C" void kernel_launch(void* const* d_in, const int* in_sizes, int n_in,
                              void* d_out, int out_size) {
    const float* pred_boxes    = (const float*)d_in[0];   // [16,8400,4]
    const float* pred_scores   = (const float*)d_in[1];   // [16,8400,80]
    const float* pred_obj      = (const float*)d_in[2];   // [16,8400]
    const float* anchor_points = (const float*)d_in[3];   // [8400,2]
    const float* stride_tensor = (const float*)d_in[4];   // [8400,1]
    const float* box_dist      = (const float*)d_in[5];   // [16,8400,64]
    const void*  class_mask    = d_in[6];                 // [16,80] bool (dtype auto-detected)
    const float* gt_boxes      = (const float*)d_in[7];   // [16,24,4]
    const void*  gt_labels     = d_in[8];                 // [16,24] int (dtype auto-detected)
    float* out = (float*)d_out;

    k_mode<<<1, 1>>>(class_mask, gt_labels);
    k_norm<<<1, 256>>>(class_mask, gt_labels);
    k_align<<<BATCH * NM, 256>>>(pred_boxes, pred_scores, anchor_points, gt_boxes);
    k_scatter<<<BATCH, 256>>>();
    dim3 g(CHUNKS, BATCH);
    k_loss<<<g, 256>>>(pred_boxes, pred_scores, pred_obj, anchor_points,
                       stride_tensor, box_dist, gt_boxes);
    k_final<<<1, 32>>>(out);
}

// round 2
// speedup vs baseline: 1.3048x; 1.3048x over previous
#include <cuda_runtime.h>
#include <cstdint>

#define BATCH 16
#define NA    8400
#define NC    80
#define NM    24
#define KTOP  13
#define REG   16
#define CH    256
#define CHUNKS 33   // ceil(8400/256)

// ---------------- device scratch ----------------
__device__ unsigned long long g_best[BATCH * NA];
__device__ unsigned long long g_cand[BATCH * NM * CHUNKS * KTOP];
__device__ float g_mx[BATCH * NA];
__device__ float g_partial[BATCH][CHUNKS][8];

// ---------------- helpers ----------------
__device__ __forceinline__ float sigmoidf(float x) { return 1.0f / (1.0f + expf(-x)); }

__device__ __forceinline__ float iou_box(float a0, float a1, float a2, float a3,
                                         float b0, float b1, float b2, float b3) {
    float lt0 = fmaxf(a0, b0), lt1 = fmaxf(a1, b1);
    float rb0 = fminf(a2, b2), rb1 = fminf(a3, b3);
    float w = fmaxf(rb0 - lt0, 0.0f), h = fmaxf(rb1 - lt1, 0.0f);
    float inter = w * h;
    float aa = fmaxf(a2 - a0, 0.0f) * fmaxf(a3 - a1, 0.0f);
    float ab = fmaxf(b2 - b0, 0.0f) * fmaxf(b3 - b1, 0.0f);
    return inter / (aa + ab - inter + 1e-7f);
}

// dtype auto-detect (validated in round 1): cmask float32/int32/uint8, labels int32/float32
__device__ __forceinline__ void detect_modes(const void* cm, const void* lab, int b,
                                             int* cmode_out, int* lmode_out) {
    const unsigned* cw = (const unsigned*)cm;
    int cmode;
    if (cw[0] == 0x3F800000u) cmode = 0;
    else {
        cmode = 1;
        for (int i = 0; i < 80; i++) if (cw[i] > 1u) { cmode = 2; break; }
    }
    const unsigned* lw = (const unsigned*)lab;
    int lm = 0;
    for (int i = 0; i < NM; i++) if (lw[b * NM + i] > 1000u) { lm = 1; break; }
    *cmode_out = cmode; *lmode_out = lm;
}

__device__ __forceinline__ float load_cmask(const void* cm, int cmode, int b, int c) {
    float v;
    if (cmode == 0)      v = ((const float*)cm)[b * NC + c];
    else if (cmode == 1) v = (float)(((const int*)cm)[b * NC + c] != 0);
    else                 v = (float)(((const unsigned char*)cm)[b * NC + c] != 0);
    return (v != 0.0f) ? 1.0f : 0.0f;
}

__device__ __forceinline__ int load_label(const void* lab, int lmode, int b, int g) {
    return lmode ? (int)(((const float*)lab)[b * NM + g]) : ((const int*)lab)[b * NM + g];
}

// ============ k_main: scores read (coalesced, once), masked max, align, local top-13 ============
__global__ __launch_bounds__(256) void k_main(const float* __restrict__ pb,
                                              const float* __restrict__ ps,
                                              const float* __restrict__ ap,
                                              const float* __restrict__ gtb,
                                              const void* __restrict__ cm_raw,
                                              const void* __restrict__ lab_raw) {
    __shared__ float cm_s[NC];
    __shared__ int   lab_s[NM];
    __shared__ int   val_s[NM];
    __shared__ float4 gtb_s[NM];
    __shared__ int   det_s[2];
    __shared__ float srow[8][84];
    __shared__ float align_s[NM][CH + 1];

    int chunk = blockIdx.x, b = blockIdx.y, t = threadIdx.x;
    int lane = t & 31, w = t >> 5;
    int nbase = chunk * CH;

    if (t == 0) detect_modes(cm_raw, lab_raw, b, &det_s[0], &det_s[1]);
    __syncthreads();
    int cmode = det_s[0], lmode = det_s[1];

    if (t < NC) cm_s[t] = load_cmask(cm_raw, cmode, b, t);
    if (t < NM) {
        int lb = load_label(lab_raw, lmode, b, t);
        lab_s[t] = min(max(lb, 0), NC - 1);
        val_s[t] = (lb >= 0 && lb < NC) ? 1 : 0;
        gtb_s[t] = ((const float4*)gtb)[b * NM + t];
    }
    __syncthreads();
    if (t < NM) val_s[t] = val_s[t] && (cm_s[lab_s[t]] != 0.0f);
#pragma unroll 4
    for (int g = 0; g < NM; g++) align_s[g][t] = -1.0f;
    if (nbase + t < NA) g_best[b * NA + nbase + t] = 0ull;
    __syncthreads();

    // mask bits per lane
    float cmr0 = cm_s[lane], cmr1 = cm_s[lane + 32];
    float cmr2 = (lane < 16) ? cm_s[lane + 64] : 0.0f;

    int a0 = nbase + w * 32;
    int alim = min(32, NA - a0);          // warp-uniform
    const float* base = ps + ((size_t)b * NA) * NC;

    if (alim > 0) {
        // prefetch first
        const float* sr = base + (size_t)(a0)*NC;
        float p0 = sr[lane], p1 = sr[lane + 32];
        float p2 = (lane < 16) ? sr[lane + 64] : 0.0f;

        for (int a = 0; a < alim; a++) {
            int n = a0 + a;
            float s0 = p0, s1 = p1, s2 = p2;
            if (a + 1 < alim) {
                const float* srn = base + (size_t)(n + 1) * NC;
                p0 = srn[lane]; p1 = srn[lane + 32];
                p2 = (lane < 16) ? srn[lane + 64] : 0.0f;
            }
            // masked max
            float m = fmaxf(cmr0 != 0.0f ? s0 : -1e30f, cmr1 != 0.0f ? s1 : -1e30f);
            if (lane < 16 && cmr2 != 0.0f) m = fmaxf(m, s2);
#pragma unroll
            for (int o = 16; o > 0; o >>= 1) m = fmaxf(m, __shfl_xor_sync(~0u, m, o));
            if (lane == 0) g_mx[b * NA + n] = m;
            // stage row
            srow[w][lane] = s0; srow[w][lane + 32] = s1;
            if (lane < 16) srow[w][lane + 64] = s2;
            __syncwarp();
            // align for lane-th GT
            if (lane < NM && val_s[lane]) {
                float4 gbx = gtb_s[lane];
                float2 apc = ((const float2*)ap)[n];
                if (apc.x >= gbx.x && apc.x <= gbx.z && apc.y >= gbx.y && apc.y <= gbx.w) {
                    float4 pbx = ((const float4*)pb)[(size_t)b * NA + n];
                    float iou = iou_box(pbx.x, pbx.y, pbx.z, pbx.w, gbx.x, gbx.y, gbx.z, gbx.w);
                    float s = srow[w][lab_s[lane]];
                    float cls = sigmoidf(s);
                    float i2 = iou * iou;
                    align_s[lane][n - nbase] = cls * (i2 * i2 * i2);
                }
            }
            __syncwarp();
        }
    }
    __syncthreads();

    // local top-13: warp w handles GTs w, w+8, w+16
#pragma unroll
    for (int gi = 0; gi < 3; gi++) {
        int g = w + gi * 8;
        unsigned long long key[8];
#pragma unroll
        for (int r = 0; r < 8; r++) {
            float v = align_s[g][lane + 32 * r];
            int n = nbase + lane + 32 * r;
            key[r] = (v >= 0.0f)
                ? (((unsigned long long)__float_as_uint(v) << 32) | (unsigned)(0xFFFFFFFFu - n))
                : 0ull;
        }
        unsigned long long* out = g_cand + (((size_t)b * NM + g) * CHUNKS + chunk) * KTOP;
        int k = 0;
        for (; k < KTOP; k++) {
            unsigned long long lm = key[0]; int lr = 0;
#pragma unroll
            for (int r = 1; r < 8; r++) if (key[r] > lm) { lm = key[r]; lr = r; }
            unsigned long long wm = lm;
#pragma unroll
            for (int o = 16; o > 0; o >>= 1) {
                unsigned long long oth = __shfl_xor_sync(~0u, wm, o);
                if (oth > wm) wm = oth;
            }
            if (wm == 0ull) break;
            if (lm == wm) key[lr] = 0ull;   // unique (idx embedded in key)
            if (lane == 0) out[k] = wm;
        }
        if (lane == 0) for (; k < KTOP; k++) out[k] = 0ull;
    }
}

// ============ k_merge: per-(b,g) merge 429 candidates -> top-13 -> scatter ============
__global__ __launch_bounds__(256) void k_merge() {
    int t = threadIdx.x, lane = t & 31, w = t >> 5;
    int wid = blockIdx.x * 8 + w;          // 0..383
    int b = wid / NM, g = wid % NM;
    const unsigned long long* src = g_cand + (size_t)wid * CHUNKS * KTOP;

    unsigned long long key[14];
#pragma unroll
    for (int r = 0; r < 14; r++) {
        int e = lane + 32 * r;
        key[r] = (e < CHUNKS * KTOP) ? src[e] : 0ull;
    }
    unsigned pri = (unsigned)(NM - g);
    for (int k = 0; k < KTOP; k++) {
        unsigned long long lm = key[0]; int lr = 0;
#pragma unroll
        for (int r = 1; r < 14; r++) if (key[r] > lm) { lm = key[r]; lr = r; }
        unsigned long long wm = lm;
#pragma unroll
        for (int o = 16; o > 0; o >>= 1) {
            unsigned long long oth = __shfl_xor_sync(~0u, wm, o);
            if (oth > wm) wm = oth;
        }
        if (wm == 0ull) break;
        if (lm == wm) {
            key[lr] = 0ull;
            int n = (int)(0xFFFFFFFFu - (unsigned)(wm & 0xFFFFFFFFull));
            unsigned long long key2 = (wm & 0xFFFFFFFF00000000ull) | pri;
            atomicMax(&g_best[b * NA + n], key2);
        }
    }
}

// ============ k_loss ============
__global__ __launch_bounds__(256) void k_loss(const float* __restrict__ pb,
                                              const float* __restrict__ ps,
                                              const float* __restrict__ pobj,
                                              const float* __restrict__ ap,
                                              const float* __restrict__ st,
                                              const float* __restrict__ bd,
                                              const float* __restrict__ gtb,
                                              const void* __restrict__ cm_raw,
                                              const void* __restrict__ lab_raw) {
    __shared__ float cm_s[NC];
    __shared__ int   lab_s[NM];
    __shared__ int   det_s[2];
    __shared__ float wred[8 * 8];

    int b = blockIdx.y, t = threadIdx.x;
    int lane = t & 31, w = t >> 5;
    int n = blockIdx.x * CH + t;

    if (t == 0) detect_modes(cm_raw, lab_raw, b, &det_s[0], &det_s[1]);
    __syncthreads();
    if (t < NC) cm_s[t] = load_cmask(cm_raw, det_s[0], b, t);
    if (t < NM) {
        int lb = load_label(lab_raw, det_s[1], b, t);
        lab_s[t] = min(max(lb, 0), NC - 1);
    }
    __syncthreads();

    // acc: 0 focal, 1 cnt, 2 (1-ciou), 3 matched iou, 4 ce, 5 dfl, 6 pos, 7 neg
    float acc[8];
#pragma unroll
    for (int q = 0; q < 8; q++) acc[q] = 0.0f;

    if (n < NA) {
        unsigned long long key = g_best[b * NA + n];
        bool fg = (key != 0ull);

        float x = pobj[(size_t)b * NA + n];
        float tt = fg ? 1.0f : 0.0f;
        float ce_o = fmaxf(x, 0.0f) - x * tt + log1pf(expf(-fabsf(x)));
        float prob_o = sigmoidf(x);
        float p_t = fg ? prob_o : (1.0f - prob_o);
        float af  = fg ? 0.25f  : 0.75f;
        float om  = 1.0f - p_t;
        acc[0] = ce_o * af * om * om;

        float mx = g_mx[b * NA + n];

        if (!fg) {
            acc[7] = prob_o * sigmoidf(mx);
        } else {
            int g = NM - (int)(key & 0xFFFFFFFFull);
            int lab = lab_s[g];
            const float* srow = ps + ((size_t)b * NA + n) * NC;
            float slab = srow[lab];
            float sum = 0.0f;
            for (int c = 0; c < NC; c++)
                if (cm_s[c] != 0.0f) sum += expf(srow[c] - mx);
            float lse = mx + logf(sum);
            acc[4] = lse - slab;
            acc[6] = prob_o * sigmoidf(slab);
            acc[1] = 1.0f;

            float4 a4 = ((const float4*)pb)[(size_t)b * NA + n];
            float4 b4 = ((const float4*)gtb)[b * NM + g];
            float a0 = a4.x, a1 = a4.y, a2 = a4.z, a3 = a4.w;
            float b0 = b4.x, b1 = b4.y, b2 = b4.z, b3 = b4.w;

            float iou = iou_box(a0, a1, a2, a3, b0, b1, b2, b3);
            acc[3] = iou;

            float cw = fmaxf(a2, b2) - fminf(a0, b0);
            float ch = fmaxf(a3, b3) - fminf(a1, b1);
            float c2 = cw * cw + ch * ch + 1e-7f;
            float dx = a0 + a2 - b0 - b2;
            float dy = a1 + a3 - b1 - b3;
            float rho2 = (dx * dx + dy * dy) * 0.25f;
            float w1 = a2 - a0, h1 = a3 - a1;
            float w2 = b2 - b0, h2 = b3 - b1;
            float dat = atanf(w2 / (h2 + 1e-7f)) - atanf(w1 / (h1 + 1e-7f));
            float v = (4.0f / (3.14159265358979323846f * 3.14159265358979323846f)) * dat * dat;
            float alpha = v / (v - iou + 1.0f + 1e-7f);
            float ciou = iou - rho2 / c2 - v * alpha;
            acc[2] = 1.0f - ciou;

            float2 apc = ((const float2*)ap)[n];
            float s = st[n];
            float tgt[4];
            tgt[0] = (apc.x - b0) / s;
            tgt[1] = (apc.y - b1) / s;
            tgt[2] = (b2 - apc.x) / s;
            tgt[3] = (b3 - apc.y) / s;
            const float* lrow = bd + ((size_t)b * NA + n) * (4 * REG);
            float dfl = 0.0f;
#pragma unroll
            for (int j = 0; j < 4; j++) {
                float tv = fminf(fmaxf(tgt[j], 0.0f), (float)(REG - 1) - 0.01f);
                int tl = (int)tv;
                int tr = min(tl + 1, REG - 1);
                float wl = (float)tr - tv;
                float wr = 1.0f - wl;
                const float* lg = lrow + j * REG;
                float m2 = -1e30f;
#pragma unroll
                for (int i = 0; i < REG; i++) m2 = fmaxf(m2, lg[i]);
                float s2 = 0.0f;
#pragma unroll
                for (int i = 0; i < REG; i++) s2 += expf(lg[i] - m2);
                float lse2 = m2 + logf(s2);
                dfl += (lse2 - lg[tl]) * wl + (lse2 - lg[tr]) * wr;
            }
            acc[5] = dfl;
        }
    }

    // warp-shuffle reductions (deterministic)
#pragma unroll
    for (int q = 0; q < 8; q++) {
        float v = acc[q];
#pragma unroll
        for (int o = 16; o > 0; o >>= 1) v += __shfl_xor_sync(~0u, v, o);
        if (lane == 0) wred[w * 8 + q] = v;
    }
    __syncthreads();
    if (t < 8) {
        float s = 0.0f;
#pragma unroll
        for (int ww = 0; ww < 8; ww++) s += wred[ww * 8 + t];
        g_partial[b][blockIdx.x][t] = s;
    }
}

// ============ k_final ============
__global__ void k_final(float* __restrict__ out) {
    __shared__ float img[BATCH][8];
    int t = threadIdx.x;
    if (t < BATCH) {
        float s[8];
#pragma unroll
        for (int q = 0; q < 8; q++) s[q] = 0.0f;
        for (int c = 0; c < CHUNKS; c++)
#pragma unroll
            for (int q = 0; q < 8; q++) s[q] += g_partial[t][c][q];
#pragma unroll
        for (int q = 0; q < 8; q++) img[t][q] = s[q];
    }
    __syncthreads();
    if (t == 0) {
        float tot_obj = 0, tot_iou = 0, tot_match = 0, tot_dfl = 0;
        float tot_pos = 0, miou = 0, pos = 0, neg = 0;
        for (int b = 0; b < BATCH; b++) {
            float cnt = img[b][1];
            float cs = fmaxf(cnt, 1.0f);
            tot_obj   += img[b][0] / (float)NA;
            tot_iou   += img[b][2] / cs;
            tot_match += img[b][4] / cs;
            tot_dfl   += img[b][5] / (4.0f * cs);
            tot_pos   += cnt;
            miou += img[b][3];
            pos  += img[b][6];
            neg  += img[b][7];
        }
        float tot_neg = (float)(BATCH * NA) - tot_pos;
        float nb = (float)BATCH;
        float loss = (tot_obj + tot_match + 7.5f * tot_iou + 1.5f * tot_dfl) / nb;
        out[0] = loss;
        out[1] = tot_obj / nb;
        out[2] = tot_match / nb;
        out[3] = tot_iou / nb;
        out[4] = tot_dfl / nb;
        out[5] = tot_pos;
        out[6] = tot_neg;
        out[7] = pos / fmaxf(tot_pos, 1.0f);
        out[8] = neg / fmaxf(tot_neg, 1.0f);
        out[9] = miou / fmaxf(tot_pos, 1.0f);
    }
}

// ---------------- launch ----------------
extern "C" void kernel_launch(void* const* d_in, const int* in_sizes, int n_in,
                              void* d_out, int out_size) {
    const float* pred_boxes    = (const float*)d_in[0];
    const float* pred_scores   = (const float*)d_in[1];
    const float* pred_obj      = (const float*)d_in[2];
    const float* anchor_points = (const float*)d_in[3];
    const float* stride_tensor = (const float*)d_in[4];
    const float* box_dist      = (const float*)d_in[5];
    const void*  class_mask    = d_in[6];
    const float* gt_boxes      = (const float*)d_in[7];
    const void*  gt_labels     = d_in[8];
    float* out = (float*)d_out;

    dim3 g(CHUNKS, BATCH);
    k_main<<<g, 256>>>(pred_boxes, pred_scores, anchor_points, gt_boxes,
                       class_mask, gt_labels);
    k_merge<<<48, 256>>>();
    k_loss<<<g, 256>>>(pred_boxes, pred_scores, pred_obj, anchor_points,
                       stride_tensor, box_dist, gt_boxes, class_mask, gt_labels);
    k_final<<<1, 32>>>(out);
}

// round 3
// speedup vs baseline: 1.5323x; 1.1744x over previous
#include <cuda_runtime.h>
#include <cstdint>

#define BATCH 16
#define NA    8400
#define NC    80
#define NM    24
#define KTOP  13
#define REG   16
#define CH    256
#define CHUNKS 33   // ceil(8400/256)

// ---------------- device scratch ----------------
__device__ unsigned long long g_best[BATCH * NA];
__device__ unsigned long long g_cand[BATCH * NM * CHUNKS * KTOP];
__device__ float g_mx[BATCH * NA];
__device__ float g_partial[BATCH][CHUNKS][8];

// ---------------- helpers ----------------
__device__ __forceinline__ float sigmoidf(float x) { return 1.0f / (1.0f + expf(-x)); }

__device__ __forceinline__ float iou_box(float a0, float a1, float a2, float a3,
                                         float b0, float b1, float b2, float b3) {
    float lt0 = fmaxf(a0, b0), lt1 = fmaxf(a1, b1);
    float rb0 = fminf(a2, b2), rb1 = fminf(a3, b3);
    float w = fmaxf(rb0 - lt0, 0.0f), h = fmaxf(rb1 - lt1, 0.0f);
    float inter = w * h;
    float aa = fmaxf(a2 - a0, 0.0f) * fmaxf(a3 - a1, 0.0f);
    float ab = fmaxf(b2 - b0, 0.0f) * fmaxf(b3 - b1, 0.0f);
    return inter / (aa + ab - inter + 1e-7f);
}

// dtype auto-detect (validated): cmask float32/int32/uint8, labels int32/float32
__device__ __forceinline__ void detect_modes(const void* cm, const void* lab, int b,
                                             int* cmode_out, int* lmode_out) {
    const unsigned* cw = (const unsigned*)cm;
    int cmode;
    if (cw[0] == 0x3F800000u) cmode = 0;
    else {
        cmode = 1;
        for (int i = 0; i < 80; i++) if (cw[i] > 1u) { cmode = 2; break; }
    }
    const unsigned* lw = (const unsigned*)lab;
    int lm = 0;
    for (int i = 0; i < NM; i++) if (lw[b * NM + i] > 1000u) { lm = 1; break; }
    *cmode_out = cmode; *lmode_out = lm;
}

__device__ __forceinline__ float load_cmask(const void* cm, int cmode, int b, int c) {
    float v;
    if (cmode == 0)      v = ((const float*)cm)[b * NC + c];
    else if (cmode == 1) v = (float)(((const int*)cm)[b * NC + c] != 0);
    else                 v = (float)(((const unsigned char*)cm)[b * NC + c] != 0);
    return (v != 0.0f) ? 1.0f : 0.0f;
}

__device__ __forceinline__ int load_label(const void* lab, int lmode, int b, int g) {
    return lmode ? (int)(((const float*)lab)[b * NM + g]) : ((const int*)lab)[b * NM + g];
}

// ============ k_main ============
__global__ __launch_bounds__(256) void k_main(const float* __restrict__ pb,
                                              const float* __restrict__ ps,
                                              const float* __restrict__ ap,
                                              const float* __restrict__ gtb,
                                              const void* __restrict__ cm_raw,
                                              const void* __restrict__ lab_raw) {
    __shared__ float cm_s[NC];
    __shared__ float4 cm4_s[20];
    __shared__ int   lab_s[NM];
    __shared__ int   val_s[NM];
    __shared__ float4 gtb_s[NM];
    __shared__ int   det_s[2];
    __shared__ float align_s[NM][CH + 1];

    int chunk = blockIdx.x, b = blockIdx.y, t = threadIdx.x;
    int lane = t & 31, w = t >> 5;
    int nbase = chunk * CH;

    if (t == 0) detect_modes(cm_raw, lab_raw, b, &det_s[0], &det_s[1]);
    __syncthreads();
    int cmode = det_s[0], lmode = det_s[1];

    if (t < NC) cm_s[t] = load_cmask(cm_raw, cmode, b, t);
    if (t < NM) {
        int lb = load_label(lab_raw, lmode, b, t);
        lab_s[t] = min(max(lb, 0), NC - 1);
        val_s[t] = (lb >= 0 && lb < NC) ? 1 : 0;
        gtb_s[t] = ((const float4*)gtb)[b * NM + t];
    }
    __syncthreads();
    if (t < NM) val_s[t] = val_s[t] && (cm_s[lab_s[t]] != 0.0f);
    if (t < 20) cm4_s[t] = ((const float4*)cm_s)[t];
#pragma unroll 4
    for (int g = 0; g < NM; g++) align_s[g][t] = -1.0f;
    if (nbase + t < NA) g_best[b * NA + nbase + t] = 0ull;
    __syncthreads();

    int a0 = nbase + w * 32;
    int alim = min(32, NA - a0);          // warp-uniform

    if (alim > 0) {
        const float4* row4 = (const float4*)(ps + ((size_t)b * NA + a0) * NC);
        float4 m4 = (lane < 20) ? cm4_s[lane] : make_float4(0, 0, 0, 0);
        // prefetch first row
        float4 p = (lane < 20) ? row4[lane] : make_float4(0, 0, 0, 0);

        for (int a = 0; a < alim; a++) {
            int n = a0 + a;
            float4 s4 = p;
            if (a + 1 < alim && lane < 20) p = row4[(size_t)(a + 1) * 20 + lane];

            // masked max of this lane's 4 classes
            float m = -1e30f;
            m = fmaxf(m, m4.x != 0.0f ? s4.x : -1e30f);
            m = fmaxf(m, m4.y != 0.0f ? s4.y : -1e30f);
            m = fmaxf(m, m4.z != 0.0f ? s4.z : -1e30f);
            m = fmaxf(m, m4.w != 0.0f ? s4.w : -1e30f);
#pragma unroll
            for (int o = 16; o > 0; o >>= 1) m = fmaxf(m, __shfl_xor_sync(~0u, m, o));
            if (lane == 0) g_mx[b * NA + n] = m;

            // align for lane-th GT (label score re-read: L1 hit on just-loaded row)
            if (lane < NM && val_s[lane]) {
                float4 gbx = gtb_s[lane];
                float2 apc = ((const float2*)ap)[n];
                if (apc.x >= gbx.x && apc.x <= gbx.z && apc.y >= gbx.y && apc.y <= gbx.w) {
                    float4 pbx = ((const float4*)pb)[(size_t)b * NA + n];
                    float iou = iou_box(pbx.x, pbx.y, pbx.z, pbx.w, gbx.x, gbx.y, gbx.z, gbx.w);
                    float sc = ps[((size_t)b * NA + n) * NC + lab_s[lane]];
                    float cls = sigmoidf(sc);
                    float i2 = iou * iou;
                    align_s[lane][n - nbase] = cls * (i2 * i2 * i2);
                }
            }
        }
    }
    __syncthreads();

    // local top-13: warp w handles GTs w, w+8, w+16
#pragma unroll
    for (int gi = 0; gi < 3; gi++) {
        int g = w + gi * 8;
        unsigned long long key[8];
        unsigned ball[8];
        int base[8], tot = 0;
#pragma unroll
        for (int r = 0; r < 8; r++) {
            float v = align_s[g][lane + 32 * r];
            int n = nbase + lane + 32 * r;
            key[r] = (v >= 0.0f)
                ? (((unsigned long long)__float_as_uint(v) << 32) | (unsigned)(0xFFFFFFFFu - n))
                : 0ull;
            ball[r] = __ballot_sync(~0u, key[r] != 0ull);
            base[r] = tot;
            tot += __popc(ball[r]);
        }
        unsigned long long* out = g_cand + (((size_t)b * NM + g) * CHUNKS + chunk) * KTOP;

        if (tot <= KTOP) {
            // fast path: scatter candidates unsorted via ballot prefix, zero-pad
            unsigned lt = (1u << lane) - 1u;
#pragma unroll
            for (int r = 0; r < 8; r++) {
                if (key[r] != 0ull) {
                    int slot = base[r] + __popc(ball[r] & lt);
                    out[slot] = key[r];
                }
            }
            if (lane >= tot && lane < KTOP) out[lane] = 0ull;
        } else {
            // slow path: 13 rounds of warp argmax
            for (int k = 0; k < KTOP; k++) {
                unsigned long long lm = key[0]; int lr = 0;
#pragma unroll
                for (int r = 1; r < 8; r++) if (key[r] > lm) { lm = key[r]; lr = r; }
                unsigned long long wm = lm;
#pragma unroll
                for (int o = 16; o > 0; o >>= 1) {
                    unsigned long long oth = __shfl_xor_sync(~0u, wm, o);
                    if (oth > wm) wm = oth;
                }
                if (lm == wm) key[lr] = 0ull;   // unique (idx embedded)
                if (lane == 0) out[k] = wm;
            }
        }
    }
}

// ============ k_merge: per-(b,g) merge 429 candidates -> top-13 -> scatter ============
__global__ __launch_bounds__(256) void k_merge() {
    int t = threadIdx.x, lane = t & 31, w = t >> 5;
    int wid = blockIdx.x * 8 + w;          // 0..383
    int b = wid / NM, g = wid % NM;
    const unsigned long long* src = g_cand + (size_t)wid * CHUNKS * KTOP;

    unsigned long long key[14];
#pragma unroll
    for (int r = 0; r < 14; r++) {
        int e = lane + 32 * r;
        key[r] = (e < CHUNKS * KTOP) ? src[e] : 0ull;
    }
    unsigned pri = (unsigned)(NM - g);
    for (int k = 0; k < KTOP; k++) {
        unsigned long long lm = key[0]; int lr = 0;
#pragma unroll
        for (int r = 1; r < 14; r++) if (key[r] > lm) { lm = key[r]; lr = r; }
        unsigned long long wm = lm;
#pragma unroll
        for (int o = 16; o > 0; o >>= 1) {
            unsigned long long oth = __shfl_xor_sync(~0u, wm, o);
            if (oth > wm) wm = oth;
        }
        if (wm == 0ull) break;
        if (lm == wm) {
            key[lr] = 0ull;
            int n = (int)(0xFFFFFFFFu - (unsigned)(wm & 0xFFFFFFFFull));
            unsigned long long key2 = (wm & 0xFFFFFFFF00000000ull) | pri;
            atomicMax(&g_best[b * NA + n], key2);
        }
    }
}

// ============ k_loss ============
__global__ __launch_bounds__(256) void k_loss(const float* __restrict__ pb,
                                              const float* __restrict__ ps,
                                              const float* __restrict__ pobj,
                                              const float* __restrict__ ap,
                                              const float* __restrict__ st,
                                              const float* __restrict__ bd,
                                              const float* __restrict__ gtb,
                                              const void* __restrict__ cm_raw,
                                              const void* __restrict__ lab_raw) {
    __shared__ float cm_s[NC];
    __shared__ int   lab_s[NM];
    __shared__ int   det_s[2];
    __shared__ float wred[8 * 8];

    int b = blockIdx.y, t = threadIdx.x;
    int lane = t & 31, w = t >> 5;
    int n = blockIdx.x * CH + t;

    if (t == 0) detect_modes(cm_raw, lab_raw, b, &det_s[0], &det_s[1]);
    __syncthreads();
    if (t < NC) cm_s[t] = load_cmask(cm_raw, det_s[0], b, t);
    if (t < NM) {
        int lb = load_label(lab_raw, det_s[1], b, t);
        lab_s[t] = min(max(lb, 0), NC - 1);
    }
    __syncthreads();

    // acc: 0 focal, 1 cnt, 2 (1-ciou), 3 matched iou, 4 ce, 5 dfl, 6 pos, 7 neg
    float acc[8];
#pragma unroll
    for (int q = 0; q < 8; q++) acc[q] = 0.0f;

    if (n < NA) {
        unsigned long long key = g_best[b * NA + n];
        bool fg = (key != 0ull);

        float x = pobj[(size_t)b * NA + n];
        float tt = fg ? 1.0f : 0.0f;
        float ce_o = fmaxf(x, 0.0f) - x * tt + log1pf(expf(-fabsf(x)));
        float prob_o = sigmoidf(x);
        float p_t = fg ? prob_o : (1.0f - prob_o);
        float af  = fg ? 0.25f  : 0.75f;
        float om  = 1.0f - p_t;
        acc[0] = ce_o * af * om * om;

        float mx = g_mx[b * NA + n];

        if (!fg) {
            acc[7] = prob_o * sigmoidf(mx);
        } else {
            int g = NM - (int)(key & 0xFFFFFFFFull);
            int lab = lab_s[g];
            const float* srow = ps + ((size_t)b * NA + n) * NC;
            float slab = srow[lab];
            float sum = 0.0f;
            for (int c = 0; c < NC; c++)
                if (cm_s[c] != 0.0f) sum += expf(srow[c] - mx);
            float lse = mx + logf(sum);
            acc[4] = lse - slab;
            acc[6] = prob_o * sigmoidf(slab);
            acc[1] = 1.0f;

            float4 a4 = ((const float4*)pb)[(size_t)b * NA + n];
            float4 b4 = ((const float4*)gtb)[b * NM + g];
            float a0 = a4.x, a1 = a4.y, a2 = a4.z, a3 = a4.w;
            float b0 = b4.x, b1 = b4.y, b2 = b4.z, b3 = b4.w;

            float iou = iou_box(a0, a1, a2, a3, b0, b1, b2, b3);
            acc[3] = iou;

            float cw = fmaxf(a2, b2) - fminf(a0, b0);
            float ch = fmaxf(a3, b3) - fminf(a1, b1);
            float c2 = cw * cw + ch * ch + 1e-7f;
            float dx = a0 + a2 - b0 - b2;
            float dy = a1 + a3 - b1 - b3;
            float rho2 = (dx * dx + dy * dy) * 0.25f;
            float w1 = a2 - a0, h1 = a3 - a1;
            float w2 = b2 - b0, h2 = b3 - b1;
            float dat = atanf(w2 / (h2 + 1e-7f)) - atanf(w1 / (h1 + 1e-7f));
            float v = (4.0f / (3.14159265358979323846f * 3.14159265358979323846f)) * dat * dat;
            float alpha = v / (v - iou + 1.0f + 1e-7f);
            float ciou = iou - rho2 / c2 - v * alpha;
            acc[2] = 1.0f - ciou;

            float2 apc = ((const float2*)ap)[n];
            float s = st[n];
            float tgt[4];
            tgt[0] = (apc.x - b0) / s;
            tgt[1] = (apc.y - b1) / s;
            tgt[2] = (b2 - apc.x) / s;
            tgt[3] = (b3 - apc.y) / s;
            const float* lrow = bd + ((size_t)b * NA + n) * (4 * REG);
            float dfl = 0.0f;
#pragma unroll
            for (int j = 0; j < 4; j++) {
                float tv = fminf(fmaxf(tgt[j], 0.0f), (float)(REG - 1) - 0.01f);
                int tl = (int)tv;
                int tr = min(tl + 1, REG - 1);
                float wl = (float)tr - tv;
                float wr = 1.0f - wl;
                const float* lg = lrow + j * REG;
                float m2 = -1e30f;
#pragma unroll
                for (int i = 0; i < REG; i++) m2 = fmaxf(m2, lg[i]);
                float s2 = 0.0f;
#pragma unroll
                for (int i = 0; i < REG; i++) s2 += expf(lg[i] - m2);
                float lse2 = m2 + logf(s2);
                dfl += (lse2 - lg[tl]) * wl + (lse2 - lg[tr]) * wr;
            }
            acc[5] = dfl;
        }
    }

#pragma unroll
    for (int q = 0; q < 8; q++) {
        float v = acc[q];
#pragma unroll
        for (int o = 16; o > 0; o >>= 1) v += __shfl_xor_sync(~0u, v, o);
        if (lane == 0) wred[w * 8 + q] = v;
    }
    __syncthreads();
    if (t < 8) {
        float s = 0.0f;
#pragma unroll
        for (int ww = 0; ww < 8; ww++) s += wred[ww * 8 + t];
        g_partial[b][blockIdx.x][t] = s;
    }
}

// ============ k_final (parallelized) ============
__global__ __launch_bounds__(256) void k_final(float* __restrict__ out) {
    __shared__ float img[BATCH][8];
    int t = threadIdx.x;
    if (t < BATCH * 8) {
        int b = t >> 3, q = t & 7;
        float s = 0.0f;
#pragma unroll 3
        for (int c = 0; c < CHUNKS; c++) s += g_partial[b][c][q];
        img[b][q] = s;
    }
    __syncthreads();
    if (t == 0) {
        float tot_obj = 0, tot_iou = 0, tot_match = 0, tot_dfl = 0;
        float tot_pos = 0, miou = 0, pos = 0, neg = 0;
        for (int b = 0; b < BATCH; b++) {
            float cnt = img[b][1];
            float cs = fmaxf(cnt, 1.0f);
            tot_obj   += img[b][0] / (float)NA;
            tot_iou   += img[b][2] / cs;
            tot_match += img[b][4] / cs;
            tot_dfl   += img[b][5] / (4.0f * cs);
            tot_pos   += cnt;
            miou += img[b][3];
            pos  += img[b][6];
            neg  += img[b][7];
        }
        float tot_neg = (float)(BATCH * NA) - tot_pos;
        float nb = (float)BATCH;
        float loss = (tot_obj + tot_match + 7.5f * tot_iou + 1.5f * tot_dfl) / nb;
        out[0] = loss;
        out[1] = tot_obj / nb;
        out[2] = tot_match / nb;
        out[3] = tot_iou / nb;
        out[4] = tot_dfl / nb;
        out[5] = tot_pos;
        out[6] = tot_neg;
        out[7] = pos / fmaxf(tot_pos, 1.0f);
        out[8] = neg / fmaxf(tot_neg, 1.0f);
        out[9] = miou / fmaxf(tot_pos, 1.0f);
    }
}

// ---------------- launch ----------------
extern "C" void kernel_launch(void* const* d_in, const int* in_sizes, int n_in,
                              void* d_out, int out_size) {
    const float* pred_boxes    = (const float*)d_in[0];
    const float* pred_scores   = (const float*)d_in[1];
    const float* pred_obj      = (const float*)d_in[2];
    const float* anchor_points = (const float*)d_in[3];
    const float* stride_tensor = (const float*)d_in[4];
    const float* box_dist      = (const float*)d_in[5];
    const void*  class_mask    = d_in[6];
    const float* gt_boxes      = (const float*)d_in[7];
    const void*  gt_labels     = d_in[8];
    float* out = (float*)d_out;

    dim3 g(CHUNKS, BATCH);
    k_main<<<g, 256>>>(pred_boxes, pred_scores, anchor_points, gt_boxes,
                       class_mask, gt_labels);
    k_merge<<<48, 256>>>();
    k_loss<<<g, 256>>>(pred_boxes, pred_scores, pred_obj, anchor_points,
                       stride_tensor, box_dist, gt_boxes, class_mask, gt_labels);
    k_final<<<1, 256>>>(out);
}